// round 2
// baseline (speedup 1.0000x reference)
#include <cuda_runtime.h>
#include <cstdint>

#define NDRUG 100000
#define NPROT 50000
#define EDD 800000
#define EDP 600000
#define EPD 600000
#define DD 128
#define WST 132   // padded shared stride for transposed W (kills bank conflicts)

// ---------------- scratch (static __device__, per allocation rules) ----------------
__device__ __align__(16) float g_Hdd[(size_t)NDRUG * DD];  // relu(x_drug @ Wagg_dd^T)
__device__ __align__(16) float g_Hdp[(size_t)NDRUG * DD];  // relu(x_drug @ Wagg_dp^T)
__device__ __align__(16) float g_Hpd[(size_t)NPROT * DD];  // relu(x_prot @ Wagg_pd^T)
__device__ __align__(16) float g_Sdd[(size_t)NDRUG * DD];  // sums into drug (dd)
__device__ __align__(16) float g_Spd[(size_t)NDRUG * DD];  // sums into drug (pd)
__device__ __align__(16) float g_Sdp[(size_t)NPROT * DD];  // sums into prot (dp)
__device__ int g_cdd[NDRUG];
__device__ int g_cpd[NDRUG];
__device__ int g_cdp[NPROT];

// ---------------- zero scratch ----------------
__global__ void zero_scratch() {
    int t = blockIdx.x * blockDim.x + threadIdx.x;
    int stride = gridDim.x * blockDim.x;
    float4 z = make_float4(0.f, 0.f, 0.f, 0.f);
    float4* sdd = reinterpret_cast<float4*>(g_Sdd);
    float4* spd = reinterpret_cast<float4*>(g_Spd);
    float4* sdp = reinterpret_cast<float4*>(g_Sdp);
    for (int i = t; i < NDRUG * (DD / 4); i += stride) { sdd[i] = z; spd[i] = z; }
    for (int i = t; i < NPROT * (DD / 4); i += stride) sdp[i] = z;
    for (int i = t; i < NDRUG; i += stride) { g_cdd[i] = 0; g_cpd[i] = 0; }
    for (int i = t; i < NPROT; i += stride) g_cdp[i] = 0;
}

// ---------------- GEMM + ReLU:  H[i,c] = relu( sum_k X[i,k] * W[c,k] ) ----------------
// Block: 256 threads, tile 64 rows x 128 cols. Per thread: 8 rows x 4 cols.
__global__ __launch_bounds__(256, 2) void agg_gemm_relu(
    const float* __restrict__ X, const float* __restrict__ W,
    float* __restrict__ H, int N)
{
    extern __shared__ float sm[];
    float* Wt = sm;              // [128][WST], Wt[k*WST+c] = W[c*128+k]
    float* xs = sm + DD * WST;   // [64][128]

    int tid = threadIdx.x;
    for (int j = tid; j < DD * DD; j += 256) {
        int c = j >> 7, k = j & 127;
        Wt[k * WST + c] = W[j];
    }
    int row0 = blockIdx.x * 64;
    const float4* Xv = reinterpret_cast<const float4*>(X);
    for (int j = tid; j < 64 * (DD / 4); j += 256) {
        int r = j >> 5, q = j & 31;
        float4 v = make_float4(0.f, 0.f, 0.f, 0.f);
        if (row0 + r < N) v = Xv[(size_t)(row0 + r) * (DD / 4) + q];
        *reinterpret_cast<float4*>(&xs[r * DD + q * 4]) = v;
    }
    __syncthreads();

    int ct = tid & 31, rt = tid >> 5;
    int c0 = ct * 4, r0 = rt * 8;
    float acc[8][4];
#pragma unroll
    for (int r = 0; r < 8; r++)
#pragma unroll
        for (int j = 0; j < 4; j++) acc[r][j] = 0.f;

#pragma unroll 8
    for (int k = 0; k < DD; k++) {
        float4 w = *reinterpret_cast<const float4*>(&Wt[k * WST + c0]);
#pragma unroll
        for (int r = 0; r < 8; r++) {
            float xv = xs[(r0 + r) * DD + k];
            acc[r][0] += xv * w.x;
            acc[r][1] += xv * w.y;
            acc[r][2] += xv * w.z;
            acc[r][3] += xv * w.w;
        }
    }
#pragma unroll
    for (int r = 0; r < 8; r++) {
        int row = row0 + r0 + r;
        if (row < N) {
            float4 o;
            o.x = fmaxf(acc[r][0], 0.f);
            o.y = fmaxf(acc[r][1], 0.f);
            o.z = fmaxf(acc[r][2], 0.f);
            o.w = fmaxf(acc[r][3], 0.f);
            *reinterpret_cast<float4*>(&H[(size_t)row * DD + c0]) = o;
        }
    }
}

// ---------------- edge scatter: one warp per edge, vector red to sums ----------------
__global__ __launch_bounds__(256) void edge_scatter(
    const float* __restrict__ H, const int* __restrict__ src,
    const int* __restrict__ dst, float* __restrict__ S,
    int* __restrict__ cnt, int E)
{
    int gw = (blockIdx.x * blockDim.x + threadIdx.x) >> 5;
    if (gw >= E) return;
    int lane = threadIdx.x & 31;
    int s = __ldg(&src[gw]);
    int d = __ldg(&dst[gw]);
    float4 v = *reinterpret_cast<const float4*>(&H[(size_t)s * DD + lane * 4]);
    float* p = &S[(size_t)d * DD + lane * 4];
    asm volatile("red.global.add.v4.f32 [%0], {%1,%2,%3,%4};"
                 :: "l"(p), "f"(v.x), "f"(v.y), "f"(v.z), "f"(v.w) : "memory");
    if (lane == 0) atomicAdd(&cnt[d], 1);
}

// ---------------- fused node update: agg-normalize + dual GEMM + bias + ReLU + residual + LN ----------------
// h[i,c] = relu( sum_k x[i,k]*W[c,k] + sum_k a[i,k]*W[c,128+k] + b[c] )
// out[i] = LN(h[i] + x[i]) * g + be
__global__ __launch_bounds__(256, 1) void node_update(
    const float* __restrict__ X,
    const float* __restrict__ Sa, const int* __restrict__ ca,
    const float* __restrict__ Sb, const int* __restrict__ cb,
    const float* __restrict__ W,   // [128, 256] row-major
    const float* __restrict__ b,
    const float* __restrict__ g,
    const float* __restrict__ be,
    float* __restrict__ out, int N, int two_rel)
{
    extern __shared__ float sm[];
    float* Wt1 = sm;                   // [128][WST]
    float* Wt2 = sm + DD * WST;        // [128][WST]
    float* xs  = sm + 2 * DD * WST;    // [64][128]
    float* as  = xs + 64 * DD;         // [64][128]

    int tid = threadIdx.x;
    for (int j = tid; j < DD * DD; j += 256) {
        int c = j >> 7, k = j & 127;
        Wt1[k * WST + c] = W[c * 256 + k];
        Wt2[k * WST + c] = W[c * 256 + 128 + k];
    }
    int row0 = blockIdx.x * 64;
    for (int j = tid; j < 64 * (DD / 4); j += 256) {
        int r = j >> 5, q = j & 31;
        int row = row0 + r;
        float4 xv = make_float4(0.f, 0.f, 0.f, 0.f);
        float4 av = make_float4(0.f, 0.f, 0.f, 0.f);
        if (row < N) {
            xv = *reinterpret_cast<const float4*>(&X[(size_t)row * DD + q * 4]);
            float ia = 1.0f / fmaxf((float)__ldg(&ca[row]), 1.0f);
            float4 sa = *reinterpret_cast<const float4*>(&Sa[(size_t)row * DD + q * 4]);
            if (two_rel) {
                float ib = 1.0f / fmaxf((float)__ldg(&cb[row]), 1.0f);
                float4 sb = *reinterpret_cast<const float4*>(&Sb[(size_t)row * DD + q * 4]);
                av.x = 0.5f * (sa.x * ia + sb.x * ib);
                av.y = 0.5f * (sa.y * ia + sb.y * ib);
                av.z = 0.5f * (sa.z * ia + sb.z * ib);
                av.w = 0.5f * (sa.w * ia + sb.w * ib);
            } else {
                av.x = sa.x * ia; av.y = sa.y * ia;
                av.z = sa.z * ia; av.w = sa.w * ia;
            }
        }
        *reinterpret_cast<float4*>(&xs[r * DD + q * 4]) = xv;
        *reinterpret_cast<float4*>(&as[r * DD + q * 4]) = av;
    }
    __syncthreads();

    int ct = tid & 31, rt = tid >> 5;
    int c0 = ct * 4, r0 = rt * 8;
    float acc[8][4];
#pragma unroll
    for (int r = 0; r < 8; r++)
#pragma unroll
        for (int j = 0; j < 4; j++) acc[r][j] = 0.f;

#pragma unroll 4
    for (int k = 0; k < DD; k++) {
        float4 w1 = *reinterpret_cast<const float4*>(&Wt1[k * WST + c0]);
        float4 w2 = *reinterpret_cast<const float4*>(&Wt2[k * WST + c0]);
#pragma unroll
        for (int r = 0; r < 8; r++) {
            float xv = xs[(r0 + r) * DD + k];
            float av = as[(r0 + r) * DD + k];
            acc[r][0] += xv * w1.x + av * w2.x;
            acc[r][1] += xv * w1.y + av * w2.y;
            acc[r][2] += xv * w1.z + av * w2.z;
            acc[r][3] += xv * w1.w + av * w2.w;
        }
    }
    float4 bb = *reinterpret_cast<const float4*>(&b[c0]);
    __syncthreads();   // everyone done reading Wt1 -> reuse as h staging
    float* hs = Wt1;   // [64][128]
#pragma unroll
    for (int r = 0; r < 8; r++) {
        int rl = r0 + r;
        float4 o;
        o.x = fmaxf(acc[r][0] + bb.x, 0.f) + xs[rl * DD + c0 + 0];
        o.y = fmaxf(acc[r][1] + bb.y, 0.f) + xs[rl * DD + c0 + 1];
        o.z = fmaxf(acc[r][2] + bb.z, 0.f) + xs[rl * DD + c0 + 2];
        o.w = fmaxf(acc[r][3] + bb.w, 0.f) + xs[rl * DD + c0 + 3];
        *reinterpret_cast<float4*>(&hs[rl * DD + c0]) = o;
    }
    __syncthreads();

    // LayerNorm: warp rt handles rows rt*8 .. rt*8+7; lane covers 4 columns
    int lane = tid & 31;
    float4 gg  = *reinterpret_cast<const float4*>(&g[lane * 4]);
    float4 bev = *reinterpret_cast<const float4*>(&be[lane * 4]);
    for (int r = 0; r < 8; r++) {
        int rl = rt * 8 + r;
        int row = row0 + rl;
        float4 v = *reinterpret_cast<const float4*>(&hs[rl * DD + lane * 4]);
        float s  = v.x + v.y + v.z + v.w;
        float s2 = v.x * v.x + v.y * v.y + v.z * v.z + v.w * v.w;
#pragma unroll
        for (int o_ = 16; o_; o_ >>= 1) {
            s  += __shfl_xor_sync(0xFFFFFFFFu, s, o_);
            s2 += __shfl_xor_sync(0xFFFFFFFFu, s2, o_);
        }
        float mu  = s * (1.0f / 128.0f);
        float var = s2 * (1.0f / 128.0f) - mu * mu;
        float rstd = rsqrtf(var + 1e-5f);
        if (row < N) {
            float4 o;
            o.x = (v.x - mu) * rstd * gg.x + bev.x;
            o.y = (v.y - mu) * rstd * gg.y + bev.y;
            o.z = (v.z - mu) * rstd * gg.z + bev.z;
            o.w = (v.w - mu) * rstd * gg.w + bev.w;
            *reinterpret_cast<float4*>(&out[(size_t)row * DD + lane * 4]) = o;
        }
    }
}

// ---------------- launch ----------------
extern "C" void kernel_launch(void* const* d_in, const int* in_sizes, int n_in,
                              void* d_out, int out_size)
{
    const float* x_drug  = (const float*)d_in[0];
    const float* x_prot  = (const float*)d_in[1];
    const float* Wagg_dd = (const float*)d_in[2];
    const float* Wagg_dp = (const float*)d_in[3];
    const float* Wagg_pd = (const float*)d_in[4];
    const float* W_drug  = (const float*)d_in[5];
    const float* b_drug  = (const float*)d_in[6];
    const float* W_prot  = (const float*)d_in[7];
    const float* b_prot  = (const float*)d_in[8];
    const float* g_drug  = (const float*)d_in[9];
    const float* be_drug = (const float*)d_in[10];
    const float* g_prot  = (const float*)d_in[11];
    const float* be_prot = (const float*)d_in[12];
    const int* dd_src = (const int*)d_in[13];
    const int* dd_dst = (const int*)d_in[14];
    const int* dp_src = (const int*)d_in[15];
    const int* dp_dst = (const int*)d_in[16];
    const int* pd_src = (const int*)d_in[17];
    const int* pd_dst = (const int*)d_in[18];
    float* out = (float*)d_out;

    float *Hdd, *Hdp, *Hpd, *Sdd, *Spd, *Sdp;
    int *cdd, *cpd, *cdp;
    cudaGetSymbolAddress((void**)&Hdd, g_Hdd);
    cudaGetSymbolAddress((void**)&Hdp, g_Hdp);
    cudaGetSymbolAddress((void**)&Hpd, g_Hpd);
    cudaGetSymbolAddress((void**)&Sdd, g_Sdd);
    cudaGetSymbolAddress((void**)&Spd, g_Spd);
    cudaGetSymbolAddress((void**)&Sdp, g_Sdp);
    cudaGetSymbolAddress((void**)&cdd, g_cdd);
    cudaGetSymbolAddress((void**)&cpd, g_cpd);
    cudaGetSymbolAddress((void**)&cdp, g_cdp);

    const int AGG_SMEM  = (DD * WST + 64 * DD) * (int)sizeof(float);       // 100352
    const int NODE_SMEM = (2 * DD * WST + 2 * 64 * DD) * (int)sizeof(float); // 200704
    cudaFuncSetAttribute(agg_gemm_relu, cudaFuncAttributeMaxDynamicSharedMemorySize, AGG_SMEM);
    cudaFuncSetAttribute(node_update,  cudaFuncAttributeMaxDynamicSharedMemorySize, NODE_SMEM);

    zero_scratch<<<2048, 256>>>();

    // Interleave GEMM -> scatter per relation so each scatter's working set
    // (H + S ~ 102MB) stays inside the 126MB L2.
    agg_gemm_relu<<<(NDRUG + 63) / 64, 256, AGG_SMEM>>>(x_drug, Wagg_dd, Hdd, NDRUG);
    edge_scatter<<<(EDD + 7) / 8, 256>>>(Hdd, dd_src, dd_dst, Sdd, cdd, EDD);

    agg_gemm_relu<<<(NPROT + 63) / 64, 256, AGG_SMEM>>>(x_prot, Wagg_pd, Hpd, NPROT);
    edge_scatter<<<(EPD + 7) / 8, 256>>>(Hpd, pd_src, pd_dst, Spd, cpd, EPD);

    agg_gemm_relu<<<(NDRUG + 63) / 64, 256, AGG_SMEM>>>(x_drug, Wagg_dp, Hdp, NDRUG);
    edge_scatter<<<(EDP + 7) / 8, 256>>>(Hdp, dp_src, dp_dst, Sdp, cdp, EDP);

    node_update<<<(NDRUG + 63) / 64, 256, NODE_SMEM>>>(
        x_drug, Sdd, cdd, Spd, cpd, W_drug, b_drug, g_drug, be_drug,
        out, NDRUG, 1);
    node_update<<<(NPROT + 63) / 64, 256, NODE_SMEM>>>(
        x_prot, Sdp, cdp, Sdp, cdp, W_prot, b_prot, g_prot, be_prot,
        out + (size_t)NDRUG * DD, NPROT, 0);
}

// round 3
// speedup vs baseline: 1.2244x; 1.2244x over previous
#include <cuda_runtime.h>
#include <cstdint>

#define NDRUG 100000
#define NPROT 50000
#define EDD 800000
#define EDP 600000
#define EPD 600000
#define DD 128
#define WST 132   // padded shared stride for transposed W
#define XTS 68    // padded shared stride for transposed X (aligned float4, conflict-free)

typedef unsigned long long u64;

__device__ __forceinline__ u64 pk2(float lo, float hi) {
    u64 r; asm("mov.b64 %0,{%1,%2};" : "=l"(r) : "f"(lo), "f"(hi)); return r;
}
__device__ __forceinline__ u64 dp2(float v) {
    u64 r; asm("mov.b64 %0,{%1,%1};" : "=l"(r) : "f"(v)); return r;
}
__device__ __forceinline__ void fma2(u64& d, u64 a, u64 b) {
    asm("fma.rn.f32x2 %0,%1,%2,%3;" : "=l"(d) : "l"(a), "l"(b), "l"(d));
}
__device__ __forceinline__ void up2(u64 v, float& lo, float& hi) {
    asm("mov.b64 {%0,%1},%2;" : "=f"(lo), "=f"(hi) : "l"(v));
}

// ---------------- scratch ----------------
__device__ __align__(16) float g_Hdd[(size_t)NDRUG * DD];
__device__ __align__(16) float g_Hdp[(size_t)NDRUG * DD];
__device__ __align__(16) float g_Hpd[(size_t)NPROT * DD];
__device__ __align__(16) float g_Sdd[(size_t)NDRUG * DD];
__device__ __align__(16) float g_Spd[(size_t)NDRUG * DD];
__device__ __align__(16) float g_Sdp[(size_t)NPROT * DD];
__device__ int g_cdd[NDRUG];
__device__ int g_cpd[NDRUG];
__device__ int g_cdp[NPROT];

__global__ void zero_scratch() {
    int t = blockIdx.x * blockDim.x + threadIdx.x;
    int stride = gridDim.x * blockDim.x;
    float4 z = make_float4(0.f, 0.f, 0.f, 0.f);
    float4* sdd = reinterpret_cast<float4*>(g_Sdd);
    float4* spd = reinterpret_cast<float4*>(g_Spd);
    float4* sdp = reinterpret_cast<float4*>(g_Sdp);
    for (int i = t; i < NDRUG * (DD / 4); i += stride) { sdd[i] = z; spd[i] = z; }
    for (int i = t; i < NPROT * (DD / 4); i += stride) sdp[i] = z;
    for (int i = t; i < NDRUG; i += stride) { g_cdd[i] = 0; g_cpd[i] = 0; }
    for (int i = t; i < NPROT; i += stride) g_cdp[i] = 0;
}

// ---------------- GEMM + ReLU (f32x2, row-paired accumulators) ----------------
// Tile: 64 rows x 128 cols, 256 threads, per thread 8 rows (4 pairs) x 4 cols.
__global__ __launch_bounds__(256, 2) void agg_gemm_relu(
    const float* __restrict__ X, const float* __restrict__ W,
    float* __restrict__ H, int N)
{
    extern __shared__ float sm[];
    float* Wt = sm;              // [128][WST], Wt[k*WST+c] = W[c*128+k]
    float* xt = sm + DD * WST;   // [128][XTS], xt[k*XTS+r] = X[row0+r][k]

    int tid = threadIdx.x;
    for (int j = tid; j < DD * DD; j += 256) {
        int c = j >> 7, k = j & 127;
        Wt[k * WST + c] = W[j];
    }
    int row0 = blockIdx.x * 64;
    for (int j = tid; j < 64 * 32; j += 256) {
        int r = j & 63, qg = j >> 6;
        int row = row0 + r;
        float4 v = make_float4(0.f, 0.f, 0.f, 0.f);
        if (row < N) v = *reinterpret_cast<const float4*>(&X[(size_t)row * DD + qg * 4]);
        xt[(qg * 4 + 0) * XTS + r] = v.x;
        xt[(qg * 4 + 1) * XTS + r] = v.y;
        xt[(qg * 4 + 2) * XTS + r] = v.z;
        xt[(qg * 4 + 3) * XTS + r] = v.w;
    }
    __syncthreads();

    int ct = tid & 31, rt = tid >> 5;
    int c0 = ct * 4, r0 = rt * 8;
    u64 acc[4][4];
#pragma unroll
    for (int rp = 0; rp < 4; rp++)
#pragma unroll
        for (int c = 0; c < 4; c++) acc[rp][c] = 0ull;

#pragma unroll 4
    for (int k = 0; k < DD; k++) {
        float4 xa = *reinterpret_cast<const float4*>(&xt[k * XTS + r0]);
        float4 xb = *reinterpret_cast<const float4*>(&xt[k * XTS + r0 + 4]);
        u64 xp[4] = {pk2(xa.x, xa.y), pk2(xa.z, xa.w), pk2(xb.x, xb.y), pk2(xb.z, xb.w)};
        float4 w = *reinterpret_cast<const float4*>(&Wt[k * WST + c0]);
        u64 wd[4] = {dp2(w.x), dp2(w.y), dp2(w.z), dp2(w.w)};
#pragma unroll
        for (int rp = 0; rp < 4; rp++)
#pragma unroll
            for (int c = 0; c < 4; c++) fma2(acc[rp][c], xp[rp], wd[c]);
    }

#pragma unroll
    for (int rp = 0; rp < 4; rp++) {
        float lo[4], hi[4];
#pragma unroll
        for (int c = 0; c < 4; c++) up2(acc[rp][c], lo[c], hi[c]);
        int ra = row0 + r0 + 2 * rp;
        if (ra < N) {
            float4 o = make_float4(fmaxf(lo[0], 0.f), fmaxf(lo[1], 0.f),
                                   fmaxf(lo[2], 0.f), fmaxf(lo[3], 0.f));
            *reinterpret_cast<float4*>(&H[(size_t)ra * DD + c0]) = o;
        }
        if (ra + 1 < N) {
            float4 o = make_float4(fmaxf(hi[0], 0.f), fmaxf(hi[1], 0.f),
                                   fmaxf(hi[2], 0.f), fmaxf(hi[3], 0.f));
            *reinterpret_cast<float4*>(&H[(size_t)(ra + 1) * DD + c0]) = o;
        }
    }
}

// ---------------- edge scatter ----------------
__global__ __launch_bounds__(256) void edge_scatter(
    const float* __restrict__ H, const int* __restrict__ src,
    const int* __restrict__ dst, float* __restrict__ S,
    int* __restrict__ cnt, int E)
{
    int gw = (blockIdx.x * blockDim.x + threadIdx.x) >> 5;
    if (gw >= E) return;
    int lane = threadIdx.x & 31;
    int s = __ldg(&src[gw]);
    int d = __ldg(&dst[gw]);
    float4 v = *reinterpret_cast<const float4*>(&H[(size_t)s * DD + lane * 4]);
    float* p = &S[(size_t)d * DD + lane * 4];
    asm volatile("red.global.add.v4.f32 [%0], {%1,%2,%3,%4};"
                 :: "l"(p), "f"(v.x), "f"(v.y), "f"(v.z), "f"(v.w) : "memory");
    if (lane == 0) atomicAdd(&cnt[d], 1);
}

// ---------------- fused node update (f32x2 dual GEMM + bias + ReLU + residual + LN) ----------------
__global__ __launch_bounds__(256, 1) void node_update(
    const float* __restrict__ X,
    const float* __restrict__ Sa, const int* __restrict__ ca,
    const float* __restrict__ Sb, const int* __restrict__ cb,
    const float* __restrict__ W,   // [128, 256] row-major
    const float* __restrict__ b,
    const float* __restrict__ g,
    const float* __restrict__ be,
    float* __restrict__ out, int N, int two_rel)
{
    extern __shared__ float sm[];
    float* Wt1 = sm;                     // [128][WST]
    float* Wt2 = sm + DD * WST;          // [128][WST]
    float* xt  = sm + 2 * DD * WST;      // [128][XTS]
    float* at  = xt + DD * XTS;          // [128][XTS]

    int tid = threadIdx.x;
    for (int j = tid; j < DD * DD; j += 256) {
        int c = j >> 7, k = j & 127;
        Wt1[k * WST + c] = W[c * 256 + k];
        Wt2[k * WST + c] = W[c * 256 + 128 + k];
    }
    int row0 = blockIdx.x * 64;
    for (int j = tid; j < 64 * 32; j += 256) {
        int r = j & 63, qg = j >> 6;
        int row = row0 + r;
        float4 xv = make_float4(0.f, 0.f, 0.f, 0.f);
        float4 av = make_float4(0.f, 0.f, 0.f, 0.f);
        if (row < N) {
            xv = *reinterpret_cast<const float4*>(&X[(size_t)row * DD + qg * 4]);
            float ia = 1.0f / fmaxf((float)__ldg(&ca[row]), 1.0f);
            float4 sa = *reinterpret_cast<const float4*>(&Sa[(size_t)row * DD + qg * 4]);
            if (two_rel) {
                float ib = 1.0f / fmaxf((float)__ldg(&cb[row]), 1.0f);
                float4 sb = *reinterpret_cast<const float4*>(&Sb[(size_t)row * DD + qg * 4]);
                av.x = 0.5f * (sa.x * ia + sb.x * ib);
                av.y = 0.5f * (sa.y * ia + sb.y * ib);
                av.z = 0.5f * (sa.z * ia + sb.z * ib);
                av.w = 0.5f * (sa.w * ia + sb.w * ib);
            } else {
                av.x = sa.x * ia; av.y = sa.y * ia;
                av.z = sa.z * ia; av.w = sa.w * ia;
            }
        }
        xt[(qg * 4 + 0) * XTS + r] = xv.x;
        xt[(qg * 4 + 1) * XTS + r] = xv.y;
        xt[(qg * 4 + 2) * XTS + r] = xv.z;
        xt[(qg * 4 + 3) * XTS + r] = xv.w;
        at[(qg * 4 + 0) * XTS + r] = av.x;
        at[(qg * 4 + 1) * XTS + r] = av.y;
        at[(qg * 4 + 2) * XTS + r] = av.z;
        at[(qg * 4 + 3) * XTS + r] = av.w;
    }
    __syncthreads();

    int ct = tid & 31, rt = tid >> 5;
    int c0 = ct * 4, r0 = rt * 8;
    u64 acc[4][4];
#pragma unroll
    for (int rp = 0; rp < 4; rp++)
#pragma unroll
        for (int c = 0; c < 4; c++) acc[rp][c] = 0ull;

#pragma unroll 2
    for (int k = 0; k < DD; k++) {
        float4 xa = *reinterpret_cast<const float4*>(&xt[k * XTS + r0]);
        float4 xb = *reinterpret_cast<const float4*>(&xt[k * XTS + r0 + 4]);
        float4 aa = *reinterpret_cast<const float4*>(&at[k * XTS + r0]);
        float4 ab = *reinterpret_cast<const float4*>(&at[k * XTS + r0 + 4]);
        u64 xp[4] = {pk2(xa.x, xa.y), pk2(xa.z, xa.w), pk2(xb.x, xb.y), pk2(xb.z, xb.w)};
        u64 ap[4] = {pk2(aa.x, aa.y), pk2(aa.z, aa.w), pk2(ab.x, ab.y), pk2(ab.z, ab.w)};
        float4 w1 = *reinterpret_cast<const float4*>(&Wt1[k * WST + c0]);
        float4 w2 = *reinterpret_cast<const float4*>(&Wt2[k * WST + c0]);
        u64 w1d[4] = {dp2(w1.x), dp2(w1.y), dp2(w1.z), dp2(w1.w)};
        u64 w2d[4] = {dp2(w2.x), dp2(w2.y), dp2(w2.z), dp2(w2.w)};
#pragma unroll
        for (int rp = 0; rp < 4; rp++)
#pragma unroll
            for (int c = 0; c < 4; c++) {
                fma2(acc[rp][c], xp[rp], w1d[c]);
                fma2(acc[rp][c], ap[rp], w2d[c]);
            }
    }
    float4 bb = *reinterpret_cast<const float4*>(&b[c0]);
    __syncthreads();   // all warps done reading Wt1 -> reuse as h staging
    float* hs = Wt1;   // [64][128]

#pragma unroll
    for (int rp = 0; rp < 4; rp++) {
        float lo[4], hi[4];
#pragma unroll
        for (int c = 0; c < 4; c++) up2(acc[rp][c], lo[c], hi[c]);
        int rla = r0 + 2 * rp;
        int ra = row0 + rla;
        // residual: coalesced reload of X (L2-hot)
        float4 xra = make_float4(0.f, 0.f, 0.f, 0.f);
        float4 xrb = make_float4(0.f, 0.f, 0.f, 0.f);
        if (ra < N)     xra = *reinterpret_cast<const float4*>(&X[(size_t)ra * DD + c0]);
        if (ra + 1 < N) xrb = *reinterpret_cast<const float4*>(&X[(size_t)(ra + 1) * DD + c0]);
        float4 oa, ob;
        oa.x = fmaxf(lo[0] + bb.x, 0.f) + xra.x;
        oa.y = fmaxf(lo[1] + bb.y, 0.f) + xra.y;
        oa.z = fmaxf(lo[2] + bb.z, 0.f) + xra.z;
        oa.w = fmaxf(lo[3] + bb.w, 0.f) + xra.w;
        ob.x = fmaxf(hi[0] + bb.x, 0.f) + xrb.x;
        ob.y = fmaxf(hi[1] + bb.y, 0.f) + xrb.y;
        ob.z = fmaxf(hi[2] + bb.z, 0.f) + xrb.z;
        ob.w = fmaxf(hi[3] + bb.w, 0.f) + xrb.w;
        *reinterpret_cast<float4*>(&hs[rla * DD + c0]) = oa;
        *reinterpret_cast<float4*>(&hs[(rla + 1) * DD + c0]) = ob;
    }
    __syncthreads();

    // LayerNorm: warp rt handles rows rt*8 .. rt*8+7; lane covers 4 columns
    int lane = tid & 31;
    float4 gg  = *reinterpret_cast<const float4*>(&g[lane * 4]);
    float4 bev = *reinterpret_cast<const float4*>(&be[lane * 4]);
    for (int r = 0; r < 8; r++) {
        int rl = rt * 8 + r;
        int row = row0 + rl;
        float4 v = *reinterpret_cast<const float4*>(&hs[rl * DD + lane * 4]);
        float s  = v.x + v.y + v.z + v.w;
        float s2 = v.x * v.x + v.y * v.y + v.z * v.z + v.w * v.w;
#pragma unroll
        for (int o_ = 16; o_; o_ >>= 1) {
            s  += __shfl_xor_sync(0xFFFFFFFFu, s, o_);
            s2 += __shfl_xor_sync(0xFFFFFFFFu, s2, o_);
        }
        float mu  = s * (1.0f / 128.0f);
        float var = s2 * (1.0f / 128.0f) - mu * mu;
        float rstd = rsqrtf(var + 1e-5f);
        if (row < N) {
            float4 o;
            o.x = (v.x - mu) * rstd * gg.x + bev.x;
            o.y = (v.y - mu) * rstd * gg.y + bev.y;
            o.z = (v.z - mu) * rstd * gg.z + bev.z;
            o.w = (v.w - mu) * rstd * gg.w + bev.w;
            *reinterpret_cast<float4*>(&out[(size_t)row * DD + lane * 4]) = o;
        }
    }
}

// ---------------- launch ----------------
extern "C" void kernel_launch(void* const* d_in, const int* in_sizes, int n_in,
                              void* d_out, int out_size)
{
    const float* x_drug  = (const float*)d_in[0];
    const float* x_prot  = (const float*)d_in[1];
    const float* Wagg_dd = (const float*)d_in[2];
    const float* Wagg_dp = (const float*)d_in[3];
    const float* Wagg_pd = (const float*)d_in[4];
    const float* W_drug  = (const float*)d_in[5];
    const float* b_drug  = (const float*)d_in[6];
    const float* W_prot  = (const float*)d_in[7];
    const float* b_prot  = (const float*)d_in[8];
    const float* g_drug  = (const float*)d_in[9];
    const float* be_drug = (const float*)d_in[10];
    const float* g_prot  = (const float*)d_in[11];
    const float* be_prot = (const float*)d_in[12];
    const int* dd_src = (const int*)d_in[13];
    const int* dd_dst = (const int*)d_in[14];
    const int* dp_src = (const int*)d_in[15];
    const int* dp_dst = (const int*)d_in[16];
    const int* pd_src = (const int*)d_in[17];
    const int* pd_dst = (const int*)d_in[18];
    float* out = (float*)d_out;

    float *Hdd, *Hdp, *Hpd, *Sdd, *Spd, *Sdp;
    int *cdd, *cpd, *cdp;
    cudaGetSymbolAddress((void**)&Hdd, g_Hdd);
    cudaGetSymbolAddress((void**)&Hdp, g_Hdp);
    cudaGetSymbolAddress((void**)&Hpd, g_Hpd);
    cudaGetSymbolAddress((void**)&Sdd, g_Sdd);
    cudaGetSymbolAddress((void**)&Spd, g_Spd);
    cudaGetSymbolAddress((void**)&Sdp, g_Sdp);
    cudaGetSymbolAddress((void**)&cdd, g_cdd);
    cudaGetSymbolAddress((void**)&cpd, g_cpd);
    cudaGetSymbolAddress((void**)&cdp, g_cdp);

    const int AGG_SMEM  = (DD * WST + DD * XTS) * (int)sizeof(float);           // 102400
    const int NODE_SMEM = (2 * DD * WST + 2 * DD * XTS) * (int)sizeof(float);   // 204800
    cudaFuncSetAttribute(agg_gemm_relu, cudaFuncAttributeMaxDynamicSharedMemorySize, AGG_SMEM);
    cudaFuncSetAttribute(node_update,  cudaFuncAttributeMaxDynamicSharedMemorySize, NODE_SMEM);

    zero_scratch<<<2048, 256>>>();

    agg_gemm_relu<<<(NDRUG + 63) / 64, 256, AGG_SMEM>>>(x_drug, Wagg_dd, Hdd, NDRUG);
    edge_scatter<<<(EDD + 7) / 8, 256>>>(Hdd, dd_src, dd_dst, Sdd, cdd, EDD);

    agg_gemm_relu<<<(NPROT + 63) / 64, 256, AGG_SMEM>>>(x_prot, Wagg_pd, Hpd, NPROT);
    edge_scatter<<<(EPD + 7) / 8, 256>>>(Hpd, pd_src, pd_dst, Spd, cpd, EPD);

    agg_gemm_relu<<<(NDRUG + 63) / 64, 256, AGG_SMEM>>>(x_drug, Wagg_dp, Hdp, NDRUG);
    edge_scatter<<<(EDP + 7) / 8, 256>>>(Hdp, dp_src, dp_dst, Sdp, cdp, EDP);

    node_update<<<(NDRUG + 63) / 64, 256, NODE_SMEM>>>(
        x_drug, Sdd, cdd, Spd, cpd, W_drug, b_drug, g_drug, be_drug,
        out, NDRUG, 1);
    node_update<<<(NPROT + 63) / 64, 256, NODE_SMEM>>>(
        x_prot, Sdp, cdp, Sdp, cdp, W_prot, b_prot, g_prot, be_prot,
        out + (size_t)NDRUG * DD, NPROT, 0);
}

// round 4
// speedup vs baseline: 1.4509x; 1.1849x over previous
#include <cuda_runtime.h>
#include <cstdint>

#define NDRUG 100000
#define NPROT 50000
#define EDD 800000
#define EDP 600000
#define EPD 600000
#define DD 128
#define XTS 68    // padded shared stride for transposed X

typedef unsigned long long u64;

__device__ __forceinline__ u64 pk2(float lo, float hi) {
    u64 r; asm("mov.b64 %0,{%1,%2};" : "=l"(r) : "f"(lo), "f"(hi)); return r;
}
__device__ __forceinline__ u64 dp2(float v) {
    u64 r; asm("mov.b64 %0,{%1,%1};" : "=l"(r) : "f"(v)); return r;
}
__device__ __forceinline__ void fma2(u64& d, u64 a, u64 b) {
    asm("fma.rn.f32x2 %0,%1,%2,%3;" : "=l"(d) : "l"(a), "l"(b), "l"(d));
}
__device__ __forceinline__ void up2(u64 v, float& lo, float& hi) {
    asm("mov.b64 {%0,%1},%2;" : "=f"(lo), "=f"(hi) : "l"(v));
}

// ---------------- scratch ----------------
__device__ __align__(16) float g_Hdd[(size_t)NDRUG * DD];
__device__ __align__(16) float g_Hdp[(size_t)NDRUG * DD];
__device__ __align__(16) float g_Hpd[(size_t)NPROT * DD];
__device__ __align__(16) float g_Sdd[(size_t)NDRUG * DD];
__device__ __align__(16) float g_Spd[(size_t)NDRUG * DD];
__device__ __align__(16) float g_Sdp[(size_t)NPROT * DD];
__device__ int g_cdd[NDRUG];
__device__ int g_cpd[NDRUG];
__device__ int g_cdp[NPROT];
// transposed weights: Wt[k*128 + c] = W[c*128 + k]
__device__ __align__(16) float g_WtDD[DD * DD];
__device__ __align__(16) float g_WtDP[DD * DD];
__device__ __align__(16) float g_WtPD[DD * DD];
// node weights: Wt[k*256 + half*128 + c] = W[c*256 + half*128 + k]
__device__ __align__(16) float g_WtDR[DD * 2 * DD];
__device__ __align__(16) float g_WtPR[DD * 2 * DD];

__global__ void zero_scratch() {
    int t = blockIdx.x * blockDim.x + threadIdx.x;
    int stride = gridDim.x * blockDim.x;
    float4 z = make_float4(0.f, 0.f, 0.f, 0.f);
    float4* sdd = reinterpret_cast<float4*>(g_Sdd);
    float4* spd = reinterpret_cast<float4*>(g_Spd);
    float4* sdp = reinterpret_cast<float4*>(g_Sdp);
    for (int i = t; i < NDRUG * (DD / 4); i += stride) { sdd[i] = z; spd[i] = z; }
    for (int i = t; i < NPROT * (DD / 4); i += stride) sdp[i] = z;
    for (int i = t; i < NDRUG; i += stride) { g_cdd[i] = 0; g_cpd[i] = 0; }
    for (int i = t; i < NPROT; i += stride) g_cdp[i] = 0;
}

__global__ void prep_weights(const float* __restrict__ Wdd, const float* __restrict__ Wdp,
                             const float* __restrict__ Wpd, const float* __restrict__ Wdr,
                             const float* __restrict__ Wpr)
{
    int t = blockIdx.x * blockDim.x + threadIdx.x;
    int stride = gridDim.x * blockDim.x;
    for (int i = t; i < DD * DD; i += stride) {
        int c = i >> 7, k = i & 127;
        g_WtDD[k * DD + c] = Wdd[i];
        g_WtDP[k * DD + c] = Wdp[i];
        g_WtPD[k * DD + c] = Wpd[i];
    }
    for (int i = t; i < DD * 2 * DD; i += stride) {
        int c = i >> 8, col = i & 255;
        int k = col & 127, half = col >> 7;
        g_WtDR[k * 256 + half * 128 + c] = Wdr[i];
        g_WtPR[k * 256 + half * 128 + c] = Wpr[i];
    }
}

// ---------------- GEMM + ReLU (f32x2, W via L1-cached LDG) ----------------
// Tile: 64 rows x 128 cols, 256 threads, per thread 8 rows (4 pairs) x 4 cols.
__global__ __launch_bounds__(256, 3) void agg_gemm_relu(
    const float* __restrict__ X, const float* __restrict__ Wt,
    float* __restrict__ H, int N)
{
    __shared__ float xt[DD * XTS];   // xt[k*XTS+r] = X[row0+r][k]

    int tid = threadIdx.x;
    int row0 = blockIdx.x * 64;
    for (int j = tid; j < 64 * 32; j += 256) {
        int r = j & 63, qg = j >> 6;
        int row = row0 + r;
        float4 v = make_float4(0.f, 0.f, 0.f, 0.f);
        if (row < N) v = *reinterpret_cast<const float4*>(&X[(size_t)row * DD + qg * 4]);
        xt[(qg * 4 + 0) * XTS + r] = v.x;
        xt[(qg * 4 + 1) * XTS + r] = v.y;
        xt[(qg * 4 + 2) * XTS + r] = v.z;
        xt[(qg * 4 + 3) * XTS + r] = v.w;
    }
    __syncthreads();

    int ct = tid & 31, rt = tid >> 5;
    int c0 = ct * 4, r0 = rt * 8;
    u64 acc[4][4];
#pragma unroll
    for (int rp = 0; rp < 4; rp++)
#pragma unroll
        for (int c = 0; c < 4; c++) acc[rp][c] = 0ull;

#pragma unroll 4
    for (int k = 0; k < DD; k++) {
        float4 w = __ldg(reinterpret_cast<const float4*>(&Wt[k * DD + c0]));
        float4 xa = *reinterpret_cast<const float4*>(&xt[k * XTS + r0]);
        float4 xb = *reinterpret_cast<const float4*>(&xt[k * XTS + r0 + 4]);
        u64 xp[4] = {pk2(xa.x, xa.y), pk2(xa.z, xa.w), pk2(xb.x, xb.y), pk2(xb.z, xb.w)};
        u64 wd[4] = {dp2(w.x), dp2(w.y), dp2(w.z), dp2(w.w)};
#pragma unroll
        for (int rp = 0; rp < 4; rp++)
#pragma unroll
            for (int c = 0; c < 4; c++) fma2(acc[rp][c], xp[rp], wd[c]);
    }

#pragma unroll
    for (int rp = 0; rp < 4; rp++) {
        float lo[4], hi[4];
#pragma unroll
        for (int c = 0; c < 4; c++) up2(acc[rp][c], lo[c], hi[c]);
        int ra = row0 + r0 + 2 * rp;
        if (ra < N) {
            float4 o = make_float4(fmaxf(lo[0], 0.f), fmaxf(lo[1], 0.f),
                                   fmaxf(lo[2], 0.f), fmaxf(lo[3], 0.f));
            *reinterpret_cast<float4*>(&H[(size_t)ra * DD + c0]) = o;
        }
        if (ra + 1 < N) {
            float4 o = make_float4(fmaxf(hi[0], 0.f), fmaxf(hi[1], 0.f),
                                   fmaxf(hi[2], 0.f), fmaxf(hi[3], 0.f));
            *reinterpret_cast<float4*>(&H[(size_t)(ra + 1) * DD + c0]) = o;
        }
    }
}

// ---------------- edge scatter ----------------
__global__ __launch_bounds__(256) void edge_scatter(
    const float* __restrict__ H, const int* __restrict__ src,
    const int* __restrict__ dst, float* __restrict__ S,
    int* __restrict__ cnt, int E)
{
    int gw = (blockIdx.x * blockDim.x + threadIdx.x) >> 5;
    if (gw >= E) return;
    int lane = threadIdx.x & 31;
    int s = __ldg(&src[gw]);
    int d = __ldg(&dst[gw]);
    float4 v = *reinterpret_cast<const float4*>(&H[(size_t)s * DD + lane * 4]);
    float* p = &S[(size_t)d * DD + lane * 4];
    asm volatile("red.global.add.v4.f32 [%0], {%1,%2,%3,%4};"
                 :: "l"(p), "f"(v.x), "f"(v.y), "f"(v.z), "f"(v.w) : "memory");
    if (lane == 0) atomicAdd(&cnt[d], 1);
}

// ---------------- fused node update (f32x2 dual GEMM, W via L2 LDG) ----------------
__global__ __launch_bounds__(256, 2) void node_update(
    const float* __restrict__ X,
    const float* __restrict__ Sa, const int* __restrict__ ca,
    const float* __restrict__ Sb, const int* __restrict__ cb,
    const float* __restrict__ Wt,   // [128][256] transposed-packed
    const float* __restrict__ b,
    const float* __restrict__ g,
    const float* __restrict__ be,
    float* __restrict__ out, int N, int two_rel)
{
    __shared__ float xt[DD * XTS];
    __shared__ float at[DD * XTS];

    int tid = threadIdx.x;
    int row0 = blockIdx.x * 64;
    for (int j = tid; j < 64 * 32; j += 256) {
        int r = j & 63, qg = j >> 6;
        int row = row0 + r;
        float4 xv = make_float4(0.f, 0.f, 0.f, 0.f);
        float4 av = make_float4(0.f, 0.f, 0.f, 0.f);
        if (row < N) {
            xv = *reinterpret_cast<const float4*>(&X[(size_t)row * DD + qg * 4]);
            float ia = 1.0f / fmaxf((float)__ldg(&ca[row]), 1.0f);
            float4 sa = *reinterpret_cast<const float4*>(&Sa[(size_t)row * DD + qg * 4]);
            if (two_rel) {
                float ib = 1.0f / fmaxf((float)__ldg(&cb[row]), 1.0f);
                float4 sb = *reinterpret_cast<const float4*>(&Sb[(size_t)row * DD + qg * 4]);
                av.x = 0.5f * (sa.x * ia + sb.x * ib);
                av.y = 0.5f * (sa.y * ia + sb.y * ib);
                av.z = 0.5f * (sa.z * ia + sb.z * ib);
                av.w = 0.5f * (sa.w * ia + sb.w * ib);
            } else {
                av.x = sa.x * ia; av.y = sa.y * ia;
                av.z = sa.z * ia; av.w = sa.w * ia;
            }
        }
        xt[(qg * 4 + 0) * XTS + r] = xv.x;
        xt[(qg * 4 + 1) * XTS + r] = xv.y;
        xt[(qg * 4 + 2) * XTS + r] = xv.z;
        xt[(qg * 4 + 3) * XTS + r] = xv.w;
        at[(qg * 4 + 0) * XTS + r] = av.x;
        at[(qg * 4 + 1) * XTS + r] = av.y;
        at[(qg * 4 + 2) * XTS + r] = av.z;
        at[(qg * 4 + 3) * XTS + r] = av.w;
    }
    __syncthreads();

    int ct = tid & 31, rt = tid >> 5;
    int c0 = ct * 4, r0 = rt * 8;
    u64 acc[4][4];
#pragma unroll
    for (int rp = 0; rp < 4; rp++)
#pragma unroll
        for (int c = 0; c < 4; c++) acc[rp][c] = 0ull;

#pragma unroll 2
    for (int k = 0; k < DD; k++) {
        float4 w1 = __ldg(reinterpret_cast<const float4*>(&Wt[k * 256 + c0]));
        float4 w2 = __ldg(reinterpret_cast<const float4*>(&Wt[k * 256 + 128 + c0]));
        float4 xa = *reinterpret_cast<const float4*>(&xt[k * XTS + r0]);
        float4 xb = *reinterpret_cast<const float4*>(&xt[k * XTS + r0 + 4]);
        float4 aa = *reinterpret_cast<const float4*>(&at[k * XTS + r0]);
        float4 ab = *reinterpret_cast<const float4*>(&at[k * XTS + r0 + 4]);
        u64 xp[4] = {pk2(xa.x, xa.y), pk2(xa.z, xa.w), pk2(xb.x, xb.y), pk2(xb.z, xb.w)};
        u64 ap[4] = {pk2(aa.x, aa.y), pk2(aa.z, aa.w), pk2(ab.x, ab.y), pk2(ab.z, ab.w)};
        u64 w1d[4] = {dp2(w1.x), dp2(w1.y), dp2(w1.z), dp2(w1.w)};
        u64 w2d[4] = {dp2(w2.x), dp2(w2.y), dp2(w2.z), dp2(w2.w)};
#pragma unroll
        for (int rp = 0; rp < 4; rp++)
#pragma unroll
            for (int c = 0; c < 4; c++) {
                fma2(acc[rp][c], xp[rp], w1d[c]);
                fma2(acc[rp][c], ap[rp], w2d[c]);
            }
    }
    float4 bb = *reinterpret_cast<const float4*>(&b[c0]);
    __syncthreads();   // all warps done reading xt/at -> reuse xt as h staging
    float* hs = xt;    // [64][128] = 32KB, fits in xt's 34.8KB

#pragma unroll
    for (int rp = 0; rp < 4; rp++) {
        float lo[4], hi[4];
#pragma unroll
        for (int c = 0; c < 4; c++) up2(acc[rp][c], lo[c], hi[c]);
        int rla = r0 + 2 * rp;
        int ra = row0 + rla;
        float4 xra = make_float4(0.f, 0.f, 0.f, 0.f);
        float4 xrb = make_float4(0.f, 0.f, 0.f, 0.f);
        if (ra < N)     xra = *reinterpret_cast<const float4*>(&X[(size_t)ra * DD + c0]);
        if (ra + 1 < N) xrb = *reinterpret_cast<const float4*>(&X[(size_t)(ra + 1) * DD + c0]);
        float4 oa, ob;
        oa.x = fmaxf(lo[0] + bb.x, 0.f) + xra.x;
        oa.y = fmaxf(lo[1] + bb.y, 0.f) + xra.y;
        oa.z = fmaxf(lo[2] + bb.z, 0.f) + xra.z;
        oa.w = fmaxf(lo[3] + bb.w, 0.f) + xra.w;
        ob.x = fmaxf(hi[0] + bb.x, 0.f) + xrb.x;
        ob.y = fmaxf(hi[1] + bb.y, 0.f) + xrb.y;
        ob.z = fmaxf(hi[2] + bb.z, 0.f) + xrb.z;
        ob.w = fmaxf(hi[3] + bb.w, 0.f) + xrb.w;
        *reinterpret_cast<float4*>(&hs[rla * DD + c0]) = oa;
        *reinterpret_cast<float4*>(&hs[(rla + 1) * DD + c0]) = ob;
    }
    __syncthreads();

    // LayerNorm
    int lane = tid & 31;
    float4 gg  = *reinterpret_cast<const float4*>(&g[lane * 4]);
    float4 bev = *reinterpret_cast<const float4*>(&be[lane * 4]);
    for (int r = 0; r < 8; r++) {
        int rl = rt * 8 + r;
        int row = row0 + rl;
        float4 v = *reinterpret_cast<const float4*>(&hs[rl * DD + lane * 4]);
        float s  = v.x + v.y + v.z + v.w;
        float s2 = v.x * v.x + v.y * v.y + v.z * v.z + v.w * v.w;
#pragma unroll
        for (int o_ = 16; o_; o_ >>= 1) {
            s  += __shfl_xor_sync(0xFFFFFFFFu, s, o_);
            s2 += __shfl_xor_sync(0xFFFFFFFFu, s2, o_);
        }
        float mu  = s * (1.0f / 128.0f);
        float var = s2 * (1.0f / 128.0f) - mu * mu;
        float rstd = rsqrtf(var + 1e-5f);
        if (row < N) {
            float4 o;
            o.x = (v.x - mu) * rstd * gg.x + bev.x;
            o.y = (v.y - mu) * rstd * gg.y + bev.y;
            o.z = (v.z - mu) * rstd * gg.z + bev.z;
            o.w = (v.w - mu) * rstd * gg.w + bev.w;
            *reinterpret_cast<float4*>(&out[(size_t)row * DD + lane * 4]) = o;
        }
    }
}

// ---------------- launch ----------------
extern "C" void kernel_launch(void* const* d_in, const int* in_sizes, int n_in,
                              void* d_out, int out_size)
{
    const float* x_drug  = (const float*)d_in[0];
    const float* x_prot  = (const float*)d_in[1];
    const float* Wagg_dd = (const float*)d_in[2];
    const float* Wagg_dp = (const float*)d_in[3];
    const float* Wagg_pd = (const float*)d_in[4];
    const float* W_drug  = (const float*)d_in[5];
    const float* b_drug  = (const float*)d_in[6];
    const float* W_prot  = (const float*)d_in[7];
    const float* b_prot  = (const float*)d_in[8];
    const float* g_drug  = (const float*)d_in[9];
    const float* be_drug = (const float*)d_in[10];
    const float* g_prot  = (const float*)d_in[11];
    const float* be_prot = (const float*)d_in[12];
    const int* dd_src = (const int*)d_in[13];
    const int* dd_dst = (const int*)d_in[14];
    const int* dp_src = (const int*)d_in[15];
    const int* dp_dst = (const int*)d_in[16];
    const int* pd_src = (const int*)d_in[17];
    const int* pd_dst = (const int*)d_in[18];
    float* out = (float*)d_out;

    float *Hdd, *Hdp, *Hpd, *Sdd, *Spd, *Sdp;
    float *WtDD, *WtDP, *WtPD, *WtDR, *WtPR;
    int *cdd, *cpd, *cdp;
    cudaGetSymbolAddress((void**)&Hdd, g_Hdd);
    cudaGetSymbolAddress((void**)&Hdp, g_Hdp);
    cudaGetSymbolAddress((void**)&Hpd, g_Hpd);
    cudaGetSymbolAddress((void**)&Sdd, g_Sdd);
    cudaGetSymbolAddress((void**)&Spd, g_Spd);
    cudaGetSymbolAddress((void**)&Sdp, g_Sdp);
    cudaGetSymbolAddress((void**)&cdd, g_cdd);
    cudaGetSymbolAddress((void**)&cpd, g_cpd);
    cudaGetSymbolAddress((void**)&cdp, g_cdp);
    cudaGetSymbolAddress((void**)&WtDD, g_WtDD);
    cudaGetSymbolAddress((void**)&WtDP, g_WtDP);
    cudaGetSymbolAddress((void**)&WtPD, g_WtPD);
    cudaGetSymbolAddress((void**)&WtDR, g_WtDR);
    cudaGetSymbolAddress((void**)&WtPR, g_WtPR);

    zero_scratch<<<2048, 256>>>();
    prep_weights<<<256, 256>>>(Wagg_dd, Wagg_dp, Wagg_pd, W_drug, W_prot);

    agg_gemm_relu<<<(NDRUG + 63) / 64, 256>>>(x_drug, WtDD, Hdd, NDRUG);
    edge_scatter<<<(EDD + 7) / 8, 256>>>(Hdd, dd_src, dd_dst, Sdd, cdd, EDD);

    agg_gemm_relu<<<(NPROT + 63) / 64, 256>>>(x_prot, WtPD, Hpd, NPROT);
    edge_scatter<<<(EPD + 7) / 8, 256>>>(Hpd, pd_src, pd_dst, Spd, cpd, EPD);

    agg_gemm_relu<<<(NDRUG + 63) / 64, 256>>>(x_drug, WtDP, Hdp, NDRUG);
    edge_scatter<<<(EDP + 7) / 8, 256>>>(Hdp, dp_src, dp_dst, Sdp, cdp, EDP);

    node_update<<<(NDRUG + 63) / 64, 256>>>(
        x_drug, Sdd, cdd, Spd, cpd, WtDR, b_drug, g_drug, be_drug,
        out, NDRUG, 1);
    node_update<<<(NPROT + 63) / 64, 256>>>(
        x_prot, Sdp, cdp, Sdp, cdp, WtPR, b_prot, g_prot, be_prot,
        out + (size_t)NDRUG * DD, NPROT, 0);
}

// round 5
// speedup vs baseline: 1.6864x; 1.1623x over previous
#include <cuda_runtime.h>
#include <cstdint>

#define NDRUG 100000
#define NPROT 50000
#define EDD 800000
#define EDP 600000
#define EPD 600000
#define DD 128
#define XTS 68

typedef unsigned long long u64;

__device__ __forceinline__ u64 pk2(float lo, float hi) {
    u64 r; asm("mov.b64 %0,{%1,%2};" : "=l"(r) : "f"(lo), "f"(hi)); return r;
}
__device__ __forceinline__ u64 dp2(float v) {
    u64 r; asm("mov.b64 %0,{%1,%1};" : "=l"(r) : "f"(v)); return r;
}
__device__ __forceinline__ void fma2(u64& d, u64 a, u64 b) {
    asm("fma.rn.f32x2 %0,%1,%2,%3;" : "=l"(d) : "l"(a), "l"(b), "l"(d));
}
__device__ __forceinline__ void up2(u64 v, float& lo, float& hi) {
    asm("mov.b64 {%0,%1},%2;" : "=f"(lo), "=f"(hi) : "l"(v));
}

// ---------------- scratch ----------------
__device__ __align__(16) float g_Hdd[(size_t)NDRUG * DD];
__device__ __align__(16) float g_Hdp[(size_t)NDRUG * DD];
__device__ __align__(16) float g_Hpd[(size_t)NPROT * DD];
__device__ __align__(16) float g_Adrug[(size_t)NDRUG * DD];  // final agg for drug
__device__ __align__(16) float g_Aprot[(size_t)NPROT * DD];  // final agg for prot
// CSR
__device__ __align__(16) int g_cnt_dd[NDRUG];
__device__ __align__(16) int g_cnt_pd[NDRUG];
__device__ __align__(16) int g_cnt_dp[NPROT];
__device__ __align__(16) int g_off_dd[NDRUG + 4];
__device__ __align__(16) int g_off_pd[NDRUG + 4];
__device__ __align__(16) int g_off_dp[NPROT + 4];
__device__ __align__(16) int g_cur_dd[NDRUG + 4];
__device__ __align__(16) int g_cur_pd[NDRUG + 4];
__device__ __align__(16) int g_cur_dp[NPROT + 4];
__device__ int g_esrc_dd[EDD];
__device__ int g_esrc_pd[EPD];
__device__ int g_esrc_dp[EDP];
// transposed weights
__device__ __align__(16) float g_WtDD[DD * DD];
__device__ __align__(16) float g_WtDP[DD * DD];
__device__ __align__(16) float g_WtPD[DD * DD];
__device__ __align__(16) float g_WtDR[DD * 2 * DD];
__device__ __align__(16) float g_WtPR[DD * 2 * DD];

// ---------------- CSR build ----------------
__global__ void zero_counts() {
    int t = blockIdx.x * blockDim.x + threadIdx.x;
    int stride = gridDim.x * blockDim.x;
    for (int i = t; i < NDRUG; i += stride) { g_cnt_dd[i] = 0; g_cnt_pd[i] = 0; }
    for (int i = t; i < NPROT; i += stride) g_cnt_dp[i] = 0;
}

__global__ void count_edges(const int* __restrict__ dst, int* __restrict__ cnt, int E) {
    int t = blockIdx.x * blockDim.x + threadIdx.x;
    if (t < E) atomicAdd(&cnt[__ldg(&dst[t])], 1);
}

// one block per relation; 1024 threads, int4 per thread per pass
__global__ __launch_bounds__(1024, 1) void scan_counts() {
    const int* cnt; int* offs; int* cur; int n;
    if (blockIdx.x == 0)      { cnt = g_cnt_dd; offs = g_off_dd; cur = g_cur_dd; n = NDRUG; }
    else if (blockIdx.x == 1) { cnt = g_cnt_pd; offs = g_off_pd; cur = g_cur_pd; n = NDRUG; }
    else                      { cnt = g_cnt_dp; offs = g_off_dp; cur = g_cur_dp; n = NPROT; }
    __shared__ int wsum[32];
    __shared__ int carry_s;
    int tid = threadIdx.x, lane = tid & 31, wid = tid >> 5;
    if (tid == 0) carry_s = 0;
    __syncthreads();
    for (int base = 0; base < n; base += 4096) {
        int i0 = base + tid * 4;
        int4 c = make_int4(0, 0, 0, 0);
        if (i0 < n) c = *reinterpret_cast<const int4*>(&cnt[i0]);
        int tot = c.x + c.y + c.z + c.w;
        int incl = tot;
#pragma unroll
        for (int o = 1; o < 32; o <<= 1) {
            int v = __shfl_up_sync(0xFFFFFFFFu, incl, o);
            if (lane >= o) incl += v;
        }
        if (lane == 31) wsum[wid] = incl;
        __syncthreads();
        if (wid == 0) {
            int v = wsum[lane];
            int wincl = v;
#pragma unroll
            for (int o = 1; o < 32; o <<= 1) {
                int t2 = __shfl_up_sync(0xFFFFFFFFu, wincl, o);
                if (lane >= o) wincl += t2;
            }
            wsum[lane] = wincl - v;
        }
        __syncthreads();
        int excl = carry_s + wsum[wid] + incl - tot;
        if (i0 < n) {
            int e0 = excl, e1 = e0 + c.x, e2 = e1 + c.y, e3 = e2 + c.z;
            *reinterpret_cast<int4*>(&offs[i0]) = make_int4(e0, e1, e2, e3);
            *reinterpret_cast<int4*>(&cur[i0])  = make_int4(e0, e1, e2, e3);
        }
        __syncthreads();
        if (tid == 1023) carry_s = excl + tot;
        __syncthreads();
    }
    if (tid == 0) offs[n] = carry_s;
}

__global__ void fill_edges(const int* __restrict__ src, const int* __restrict__ dst,
                           int* __restrict__ cur, int* __restrict__ esrc, int E) {
    int t = blockIdx.x * blockDim.x + threadIdx.x;
    if (t < E) {
        int d = __ldg(&dst[t]);
        int slot = atomicAdd(&cur[d], 1);
        esrc[slot] = __ldg(&src[t]);
    }
}

__global__ void prep_weights(const float* __restrict__ Wdd, const float* __restrict__ Wdp,
                             const float* __restrict__ Wpd, const float* __restrict__ Wdr,
                             const float* __restrict__ Wpr)
{
    int t = blockIdx.x * blockDim.x + threadIdx.x;
    int stride = gridDim.x * blockDim.x;
    for (int i = t; i < DD * DD; i += stride) {
        int c = i >> 7, k = i & 127;
        g_WtDD[k * DD + c] = Wdd[i];
        g_WtDP[k * DD + c] = Wdp[i];
        g_WtPD[k * DD + c] = Wpd[i];
    }
    for (int i = t; i < DD * 2 * DD; i += stride) {
        int c = i >> 8, col = i & 255;
        int k = col & 127, half = col >> 7;
        g_WtDR[k * 256 + half * 128 + c] = Wdr[i];
        g_WtPR[k * 256 + half * 128 + c] = Wpr[i];
    }
}

// ---------------- GEMM + ReLU (f32x2, W via L1-cached LDG) ----------------
__global__ __launch_bounds__(256, 3) void agg_gemm_relu(
    const float* __restrict__ X, const float* __restrict__ Wt,
    float* __restrict__ H, int N)
{
    __shared__ float xt[DD * XTS];

    int tid = threadIdx.x;
    int row0 = blockIdx.x * 64;
    for (int j = tid; j < 64 * 32; j += 256) {
        int r = j & 63, qg = j >> 6;
        int row = row0 + r;
        float4 v = make_float4(0.f, 0.f, 0.f, 0.f);
        if (row < N) v = *reinterpret_cast<const float4*>(&X[(size_t)row * DD + qg * 4]);
        xt[(qg * 4 + 0) * XTS + r] = v.x;
        xt[(qg * 4 + 1) * XTS + r] = v.y;
        xt[(qg * 4 + 2) * XTS + r] = v.z;
        xt[(qg * 4 + 3) * XTS + r] = v.w;
    }
    __syncthreads();

    int ct = tid & 31, rt = tid >> 5;
    int c0 = ct * 4, r0 = rt * 8;
    u64 acc[4][4];
#pragma unroll
    for (int rp = 0; rp < 4; rp++)
#pragma unroll
        for (int c = 0; c < 4; c++) acc[rp][c] = 0ull;

#pragma unroll 4
    for (int k = 0; k < DD; k++) {
        float4 w = __ldg(reinterpret_cast<const float4*>(&Wt[k * DD + c0]));
        float4 xa = *reinterpret_cast<const float4*>(&xt[k * XTS + r0]);
        float4 xb = *reinterpret_cast<const float4*>(&xt[k * XTS + r0 + 4]);
        u64 xp[4] = {pk2(xa.x, xa.y), pk2(xa.z, xa.w), pk2(xb.x, xb.y), pk2(xb.z, xb.w)};
        u64 wd[4] = {dp2(w.x), dp2(w.y), dp2(w.z), dp2(w.w)};
#pragma unroll
        for (int rp = 0; rp < 4; rp++)
#pragma unroll
            for (int c = 0; c < 4; c++) fma2(acc[rp][c], xp[rp], wd[c]);
    }

#pragma unroll
    for (int rp = 0; rp < 4; rp++) {
        float lo[4], hi[4];
#pragma unroll
        for (int c = 0; c < 4; c++) up2(acc[rp][c], lo[c], hi[c]);
        int ra = row0 + r0 + 2 * rp;
        if (ra < N) {
            float4 o = make_float4(fmaxf(lo[0], 0.f), fmaxf(lo[1], 0.f),
                                   fmaxf(lo[2], 0.f), fmaxf(lo[3], 0.f));
            *reinterpret_cast<float4*>(&H[(size_t)ra * DD + c0]) = o;
        }
        if (ra + 1 < N) {
            float4 o = make_float4(fmaxf(hi[0], 0.f), fmaxf(hi[1], 0.f),
                                   fmaxf(hi[2], 0.f), fmaxf(hi[3], 0.f));
            *reinterpret_cast<float4*>(&H[(size_t)(ra + 1) * DD + c0]) = o;
        }
    }
}

// ---------------- CSR gather: one warp per dst node, register accumulation ----------------
// mode 0: A[w] = mean(H[src])           mode 1: A[w] = 0.5*(A[w] + mean(H[src]))
__global__ __launch_bounds__(256) void edge_gather(
    const float* __restrict__ H, const int* __restrict__ esrc,
    const int* __restrict__ offs, float* __restrict__ A, int N, int mode)
{
    int w = (blockIdx.x * blockDim.x + threadIdx.x) >> 5;
    if (w >= N) return;
    int lane = threadIdx.x & 31;
    int beg = __ldg(&offs[w]), end = __ldg(&offs[w + 1]);
    float4 acc = make_float4(0.f, 0.f, 0.f, 0.f);
    int e = beg;
    for (; e + 4 <= end; e += 4) {
        int s0 = __ldg(&esrc[e]);
        int s1 = __ldg(&esrc[e + 1]);
        int s2 = __ldg(&esrc[e + 2]);
        int s3 = __ldg(&esrc[e + 3]);
        float4 v0 = __ldg(reinterpret_cast<const float4*>(&H[(size_t)s0 * DD + lane * 4]));
        float4 v1 = __ldg(reinterpret_cast<const float4*>(&H[(size_t)s1 * DD + lane * 4]));
        float4 v2 = __ldg(reinterpret_cast<const float4*>(&H[(size_t)s2 * DD + lane * 4]));
        float4 v3 = __ldg(reinterpret_cast<const float4*>(&H[(size_t)s3 * DD + lane * 4]));
        acc.x += (v0.x + v1.x) + (v2.x + v3.x);
        acc.y += (v0.y + v1.y) + (v2.y + v3.y);
        acc.z += (v0.z + v1.z) + (v2.z + v3.z);
        acc.w += (v0.w + v1.w) + (v2.w + v3.w);
    }
    for (; e < end; e++) {
        int s = __ldg(&esrc[e]);
        float4 v = __ldg(reinterpret_cast<const float4*>(&H[(size_t)s * DD + lane * 4]));
        acc.x += v.x; acc.y += v.y; acc.z += v.z; acc.w += v.w;
    }
    float inv = 1.0f / fmaxf((float)(end - beg), 1.0f);
    float4 o = make_float4(acc.x * inv, acc.y * inv, acc.z * inv, acc.w * inv);
    float* p = &A[(size_t)w * DD + lane * 4];
    if (mode) {
        float4 prev = *reinterpret_cast<const float4*>(p);
        o.x = 0.5f * (prev.x + o.x);
        o.y = 0.5f * (prev.y + o.y);
        o.z = 0.5f * (prev.z + o.z);
        o.w = 0.5f * (prev.w + o.w);
    }
    *reinterpret_cast<float4*>(p) = o;
}

// ---------------- fused node update (f32x2 dual GEMM + bias + ReLU + residual + LN) ----------------
__global__ __launch_bounds__(256, 2) void node_update(
    const float* __restrict__ X,
    const float* __restrict__ A,    // final aggregated features [N,128]
    const float* __restrict__ Wt,   // [128][256] transposed-packed
    const float* __restrict__ b,
    const float* __restrict__ g,
    const float* __restrict__ be,
    float* __restrict__ out, int N)
{
    __shared__ float xt[DD * XTS];
    __shared__ float at[DD * XTS];

    int tid = threadIdx.x;
    int row0 = blockIdx.x * 64;
    for (int j = tid; j < 64 * 32; j += 256) {
        int r = j & 63, qg = j >> 6;
        int row = row0 + r;
        float4 xv = make_float4(0.f, 0.f, 0.f, 0.f);
        float4 av = make_float4(0.f, 0.f, 0.f, 0.f);
        if (row < N) {
            xv = *reinterpret_cast<const float4*>(&X[(size_t)row * DD + qg * 4]);
            av = *reinterpret_cast<const float4*>(&A[(size_t)row * DD + qg * 4]);
        }
        xt[(qg * 4 + 0) * XTS + r] = xv.x;
        xt[(qg * 4 + 1) * XTS + r] = xv.y;
        xt[(qg * 4 + 2) * XTS + r] = xv.z;
        xt[(qg * 4 + 3) * XTS + r] = xv.w;
        at[(qg * 4 + 0) * XTS + r] = av.x;
        at[(qg * 4 + 1) * XTS + r] = av.y;
        at[(qg * 4 + 2) * XTS + r] = av.z;
        at[(qg * 4 + 3) * XTS + r] = av.w;
    }
    __syncthreads();

    int ct = tid & 31, rt = tid >> 5;
    int c0 = ct * 4, r0 = rt * 8;
    u64 acc[4][4];
#pragma unroll
    for (int rp = 0; rp < 4; rp++)
#pragma unroll
        for (int c = 0; c < 4; c++) acc[rp][c] = 0ull;

#pragma unroll 2
    for (int k = 0; k < DD; k++) {
        float4 w1 = __ldg(reinterpret_cast<const float4*>(&Wt[k * 256 + c0]));
        float4 w2 = __ldg(reinterpret_cast<const float4*>(&Wt[k * 256 + 128 + c0]));
        float4 xa = *reinterpret_cast<const float4*>(&xt[k * XTS + r0]);
        float4 xb = *reinterpret_cast<const float4*>(&xt[k * XTS + r0 + 4]);
        float4 aa = *reinterpret_cast<const float4*>(&at[k * XTS + r0]);
        float4 ab = *reinterpret_cast<const float4*>(&at[k * XTS + r0 + 4]);
        u64 xp[4] = {pk2(xa.x, xa.y), pk2(xa.z, xa.w), pk2(xb.x, xb.y), pk2(xb.z, xb.w)};
        u64 ap[4] = {pk2(aa.x, aa.y), pk2(aa.z, aa.w), pk2(ab.x, ab.y), pk2(ab.z, ab.w)};
        u64 w1d[4] = {dp2(w1.x), dp2(w1.y), dp2(w1.z), dp2(w1.w)};
        u64 w2d[4] = {dp2(w2.x), dp2(w2.y), dp2(w2.z), dp2(w2.w)};
#pragma unroll
        for (int rp = 0; rp < 4; rp++)
#pragma unroll
            for (int c = 0; c < 4; c++) {
                fma2(acc[rp][c], xp[rp], w1d[c]);
                fma2(acc[rp][c], ap[rp], w2d[c]);
            }
    }
    float4 bb = *reinterpret_cast<const float4*>(&b[c0]);
    __syncthreads();
    float* hs = xt;

#pragma unroll
    for (int rp = 0; rp < 4; rp++) {
        float lo[4], hi[4];
#pragma unroll
        for (int c = 0; c < 4; c++) up2(acc[rp][c], lo[c], hi[c]);
        int rla = r0 + 2 * rp;
        int ra = row0 + rla;
        float4 xra = make_float4(0.f, 0.f, 0.f, 0.f);
        float4 xrb = make_float4(0.f, 0.f, 0.f, 0.f);
        if (ra < N)     xra = *reinterpret_cast<const float4*>(&X[(size_t)ra * DD + c0]);
        if (ra + 1 < N) xrb = *reinterpret_cast<const float4*>(&X[(size_t)(ra + 1) * DD + c0]);
        float4 oa, ob;
        oa.x = fmaxf(lo[0] + bb.x, 0.f) + xra.x;
        oa.y = fmaxf(lo[1] + bb.y, 0.f) + xra.y;
        oa.z = fmaxf(lo[2] + bb.z, 0.f) + xra.z;
        oa.w = fmaxf(lo[3] + bb.w, 0.f) + xra.w;
        ob.x = fmaxf(hi[0] + bb.x, 0.f) + xrb.x;
        ob.y = fmaxf(hi[1] + bb.y, 0.f) + xrb.y;
        ob.z = fmaxf(hi[2] + bb.z, 0.f) + xrb.z;
        ob.w = fmaxf(hi[3] + bb.w, 0.f) + xrb.w;
        *reinterpret_cast<float4*>(&hs[rla * DD + c0]) = oa;
        *reinterpret_cast<float4*>(&hs[(rla + 1) * DD + c0]) = ob;
    }
    __syncthreads();

    int lane = tid & 31;
    float4 gg  = *reinterpret_cast<const float4*>(&g[lane * 4]);
    float4 bev = *reinterpret_cast<const float4*>(&be[lane * 4]);
    for (int r = 0; r < 8; r++) {
        int rl = rt * 8 + r;
        int row = row0 + rl;
        float4 v = *reinterpret_cast<const float4*>(&hs[rl * DD + lane * 4]);
        float s  = v.x + v.y + v.z + v.w;
        float s2 = v.x * v.x + v.y * v.y + v.z * v.z + v.w * v.w;
#pragma unroll
        for (int o_ = 16; o_; o_ >>= 1) {
            s  += __shfl_xor_sync(0xFFFFFFFFu, s, o_);
            s2 += __shfl_xor_sync(0xFFFFFFFFu, s2, o_);
        }
        float mu  = s * (1.0f / 128.0f);
        float var = s2 * (1.0f / 128.0f) - mu * mu;
        float rstd = rsqrtf(var + 1e-5f);
        if (row < N) {
            float4 o;
            o.x = (v.x - mu) * rstd * gg.x + bev.x;
            o.y = (v.y - mu) * rstd * gg.y + bev.y;
            o.z = (v.z - mu) * rstd * gg.z + bev.z;
            o.w = (v.w - mu) * rstd * gg.w + bev.w;
            *reinterpret_cast<float4*>(&out[(size_t)row * DD + lane * 4]) = o;
        }
    }
}

// ---------------- launch ----------------
extern "C" void kernel_launch(void* const* d_in, const int* in_sizes, int n_in,
                              void* d_out, int out_size)
{
    const float* x_drug  = (const float*)d_in[0];
    const float* x_prot  = (const float*)d_in[1];
    const float* Wagg_dd = (const float*)d_in[2];
    const float* Wagg_dp = (const float*)d_in[3];
    const float* Wagg_pd = (const float*)d_in[4];
    const float* W_drug  = (const float*)d_in[5];
    const float* b_drug  = (const float*)d_in[6];
    const float* W_prot  = (const float*)d_in[7];
    const float* b_prot  = (const float*)d_in[8];
    const float* g_drug  = (const float*)d_in[9];
    const float* be_drug = (const float*)d_in[10];
    const float* g_prot  = (const float*)d_in[11];
    const float* be_prot = (const float*)d_in[12];
    const int* dd_src = (const int*)d_in[13];
    const int* dd_dst = (const int*)d_in[14];
    const int* dp_src = (const int*)d_in[15];
    const int* dp_dst = (const int*)d_in[16];
    const int* pd_src = (const int*)d_in[17];
    const int* pd_dst = (const int*)d_in[18];
    float* out = (float*)d_out;

    float *Hdd, *Hdp, *Hpd, *Adrug, *Aprot;
    float *WtDD, *WtDP, *WtPD, *WtDR, *WtPR;
    int *cnt_dd, *cnt_pd, *cnt_dp;
    int *off_dd, *off_pd, *off_dp;
    int *cur_dd, *cur_pd, *cur_dp;
    int *esrc_dd, *esrc_pd, *esrc_dp;
    cudaGetSymbolAddress((void**)&Hdd, g_Hdd);
    cudaGetSymbolAddress((void**)&Hdp, g_Hdp);
    cudaGetSymbolAddress((void**)&Hpd, g_Hpd);
    cudaGetSymbolAddress((void**)&Adrug, g_Adrug);
    cudaGetSymbolAddress((void**)&Aprot, g_Aprot);
    cudaGetSymbolAddress((void**)&WtDD, g_WtDD);
    cudaGetSymbolAddress((void**)&WtDP, g_WtDP);
    cudaGetSymbolAddress((void**)&WtPD, g_WtPD);
    cudaGetSymbolAddress((void**)&WtDR, g_WtDR);
    cudaGetSymbolAddress((void**)&WtPR, g_WtPR);
    cudaGetSymbolAddress((void**)&cnt_dd, g_cnt_dd);
    cudaGetSymbolAddress((void**)&cnt_pd, g_cnt_pd);
    cudaGetSymbolAddress((void**)&cnt_dp, g_cnt_dp);
    cudaGetSymbolAddress((void**)&off_dd, g_off_dd);
    cudaGetSymbolAddress((void**)&off_pd, g_off_pd);
    cudaGetSymbolAddress((void**)&off_dp, g_off_dp);
    cudaGetSymbolAddress((void**)&cur_dd, g_cur_dd);
    cudaGetSymbolAddress((void**)&cur_pd, g_cur_pd);
    cudaGetSymbolAddress((void**)&cur_dp, g_cur_dp);
    cudaGetSymbolAddress((void**)&esrc_dd, g_esrc_dd);
    cudaGetSymbolAddress((void**)&esrc_pd, g_esrc_pd);
    cudaGetSymbolAddress((void**)&esrc_dp, g_esrc_dp);

    // CSR build
    zero_counts<<<256, 256>>>();
    prep_weights<<<256, 256>>>(Wagg_dd, Wagg_dp, Wagg_pd, W_drug, W_prot);
    count_edges<<<(EDD + 255) / 256, 256>>>(dd_dst, cnt_dd, EDD);
    count_edges<<<(EPD + 255) / 256, 256>>>(pd_dst, cnt_pd, EPD);
    count_edges<<<(EDP + 255) / 256, 256>>>(dp_dst, cnt_dp, EDP);
    scan_counts<<<3, 1024>>>();
    fill_edges<<<(EDD + 255) / 256, 256>>>(dd_src, dd_dst, cur_dd, esrc_dd, EDD);
    fill_edges<<<(EPD + 255) / 256, 256>>>(pd_src, pd_dst, cur_pd, esrc_pd, EPD);
    fill_edges<<<(EDP + 255) / 256, 256>>>(dp_src, dp_dst, cur_dp, esrc_dp, EDP);

    // GEMMs + gathers, interleaved for L2 residency
    agg_gemm_relu<<<(NDRUG + 63) / 64, 256>>>(x_drug, WtDD, Hdd, NDRUG);
    edge_gather<<<(NDRUG * 32 + 255) / 256, 256>>>(Hdd, esrc_dd, off_dd, Adrug, NDRUG, 0);

    agg_gemm_relu<<<(NPROT + 63) / 64, 256>>>(x_prot, WtPD, Hpd, NPROT);
    edge_gather<<<(NDRUG * 32 + 255) / 256, 256>>>(Hpd, esrc_pd, off_pd, Adrug, NDRUG, 1);

    agg_gemm_relu<<<(NDRUG + 63) / 64, 256>>>(x_drug, WtDP, Hdp, NDRUG);
    edge_gather<<<(NPROT * 32 + 255) / 256, 256>>>(Hdp, esrc_dp, off_dp, Aprot, NPROT, 0);

    node_update<<<(NDRUG + 63) / 64, 256>>>(
        x_drug, Adrug, WtDR, b_drug, g_drug, be_drug, out, NDRUG);
    node_update<<<(NPROT + 63) / 64, 256>>>(
        x_prot, Aprot, WtPR, b_prot, g_prot, be_prot,
        out + (size_t)NDRUG * DD, NPROT);
}